// round 1
// baseline (speedup 1.0000x reference)
#include <cuda_runtime.h>
#include <cstdint>

#define L    4096
#define TD   128
#define CH   64
#define NH   4
#define HD   32
#define NSB  4

// Scratch (static device globals are allowed; no runtime allocation)
static __device__ float Qbuf[NSB * L * TD];
static __device__ float Kbuf[NSB * L * TD];
static __device__ float Vbuf[NSB * L * TD];
static __device__ float Fbuf[NSB * L * TD];   // fused = (attn + q) * 0.5, (L,128) contiguous per sb

// Packed fp32x2 FMA (sm_100+ PTX; bit-exact fp32 per lane, 2x FFMA throughput)
__device__ __forceinline__ void ffma2(unsigned long long &d,
                                      unsigned long long a,
                                      unsigned long long b) {
    asm("fma.rn.f32x2 %0, %1, %2, %0;" : "+l"(d) : "l"(a), "l"(b));
}

__device__ __forceinline__ unsigned long long pack2(float x) {
    unsigned long long r;
    unsigned int u = __float_as_uint(x);
    asm("mov.b64 %0, {%1, %1};" : "=l"(r) : "r"(u));
    return r;
}

__device__ __forceinline__ void unpack2(unsigned long long d, float &lo, float &hi) {
    unsigned int a, b;
    asm("mov.b64 {%0, %1}, %2;" : "=r"(a), "=r"(b) : "l"(d));
    lo = __uint_as_float(a);
    hi = __uint_as_float(b);
}

// ---------------------------------------------------------------------------
// Kernel A: QKV projection.  q[b,l,t] = sum_c feat[b,c,l] * wq[t,c] + bq[t]
// grid: (L, NSB), block: 128 (one thread per output channel t)
// ---------------------------------------------------------------------------
__global__ void __launch_bounds__(128) qkv_kernel(
    const float* __restrict__ fct, const float* __restrict__ fpet,
    const float* __restrict__ wq, const float* __restrict__ bq,
    const float* __restrict__ wk, const float* __restrict__ bk,
    const float* __restrict__ wv, const float* __restrict__ bv)
{
    int l  = blockIdx.x;
    int sb = blockIdx.y;                 // sb = s*2 + b
    const float* feat = ((sb >> 1) ? fpet : fct) + (sb & 1) * (CH * L);

    __shared__ float xs[CH];
    int t = threadIdx.x;
    if (t < CH) xs[t] = feat[t * L + l];
    __syncthreads();

    float aq = bq[t], ak = bk[t], av = bv[t];
    const float* wqr = wq + t * CH;
    const float* wkr = wk + t * CH;
    const float* wvr = wv + t * CH;
#pragma unroll
    for (int c = 0; c < CH; c++) {
        float x = xs[c];
        aq = fmaf(x, wqr[c], aq);
        ak = fmaf(x, wkr[c], ak);
        av = fmaf(x, wvr[c], av);
    }
    int base = (sb * L + l) * TD + t;
    Qbuf[base] = aq;
    Kbuf[base] = ak;
    Vbuf[base] = av;
}

// ---------------------------------------------------------------------------
// Kernel B: cross attention (no max-subtraction softmax; logits are tiny).
// grid: (32 qtiles, NH, NSB), block: 128 (one query per thread).
// Writes Fbuf = 0.5 * (attn_out + q).
// ---------------------------------------------------------------------------
__global__ void __launch_bounds__(128) attn_kernel()
{
    const float SCALEV = 0.17677669529663687f;  // 32^-0.5

    int qt = blockIdx.x;
    int h  = blockIdx.y;
    int sb = blockIdx.z;
    int kvsb = sb ^ 2;                   // flip stream bit, keep batch

    const float* Qp = Qbuf + (size_t)sb   * L * TD;
    const float* Kp = Kbuf + (size_t)kvsb * L * TD;
    const float* Vp = Vbuf + (size_t)kvsb * L * TD;

    int tid  = threadIdx.x;
    int qrow = qt * 128 + tid;

    // Load this thread's q row (32 floats = 16 packed pairs)
    unsigned long long qd[16];
    const unsigned long long* qsrc =
        (const unsigned long long*)(Qp + (size_t)qrow * TD + h * HD);
#pragma unroll
    for (int i = 0; i < 16; i++) qd[i] = qsrc[i];

    unsigned long long acc[16];
#pragma unroll
    for (int i = 0; i < 16; i++) acc[i] = 0ull;
    float ssum = 0.0f;

    __shared__ float Ks[128][36];   // 36-float rows: 144B, 16B-aligned, conflict-light stores
    __shared__ float Vs[128][36];

    for (int kt = 0; kt < 32; kt++) {
        __syncthreads();
        const float4* kr = (const float4*)(Kp + (size_t)(kt * 128 + tid) * TD + h * HD);
        const float4* vr = (const float4*)(Vp + (size_t)(kt * 128 + tid) * TD + h * HD);
        float4* kd = (float4*)&Ks[tid][0];
        float4* vd = (float4*)&Vs[tid][0];
#pragma unroll
        for (int i = 0; i < 8; i++) { kd[i] = kr[i]; vd[i] = vr[i]; }
        __syncthreads();

#pragma unroll 2
        for (int j = 0; j < 128; j++) {
            const unsigned long long* kpp = (const unsigned long long*)&Ks[j][0];
            // two independent dot-product chains (latency)
            unsigned long long s2a = 0ull, s2b = 0ull;
#pragma unroll
            for (int i = 0; i < 16; i += 2) {
                ffma2(s2a, qd[i],     kpp[i]);
                ffma2(s2b, qd[i + 1], kpp[i + 1]);
            }
            float alo, ahi, blo, bhi;
            unpack2(s2a, alo, ahi);
            unpack2(s2b, blo, bhi);
            float s = (alo + ahi) + (blo + bhi);
            float p = __expf(s * SCALEV);
            ssum += p;
            unsigned long long pp = pack2(p);
            const unsigned long long* vpp = (const unsigned long long*)&Vs[j][0];
#pragma unroll
            for (int i = 0; i < 16; i++) ffma2(acc[i], pp, vpp[i]);
        }
    }

    float inv = 1.0f / ssum;
    float* outp = Fbuf + (size_t)(sb * L + qrow) * TD + h * HD;
#pragma unroll
    for (int i = 0; i < 16; i++) {
        float alo, ahi, qlo, qhi;
        unpack2(acc[i], alo, ahi);
        unpack2(qd[i],  qlo, qhi);
        outp[2 * i]     = 0.5f * (alo * inv + qlo);
        outp[2 * i + 1] = 0.5f * (ahi * inv + qhi);
    }
}

// ---------------------------------------------------------------------------
// Kernel C: output projection + residual.
// The reference's reshape is a raw reinterpretation: X[b,t,v] = Fbuf[t*L + v].
// out[s][b][c][v] = feat[b][c][v] + bo[c] + sum_t wo[c][t] * X[t,v]
// grid: (32 voxel tiles, NSB), block: 128 (one voxel per thread)
// ---------------------------------------------------------------------------
__global__ void __launch_bounds__(128) out_kernel(
    const float* __restrict__ fct, const float* __restrict__ fpet,
    const float* __restrict__ wo, const float* __restrict__ bo,
    float* __restrict__ out)
{
    int vt = blockIdx.x;
    int sb = blockIdx.y;
    int tid = threadIdx.x;
    int v = vt * 128 + tid;

    __shared__ float wos[128][66];   // wos[t][c], 66-float rows keep 8B alignment
    for (int idx = tid; idx < 128 * 64; idx += 128) {
        int c = idx >> 7;
        int t = idx & 127;
        wos[t][c] = wo[idx];         // wo[c*128 + t], coalesced read
    }
    __syncthreads();

    unsigned long long accp[32];
#pragma unroll
    for (int i = 0; i < 32; i++) accp[i] = 0ull;

    const float* F = Fbuf + (size_t)sb * L * TD;
#pragma unroll 4
    for (int t = 0; t < 128; t++) {
        float x = F[(size_t)t * L + v];
        unsigned long long xp = pack2(x);
        const unsigned long long* wp = (const unsigned long long*)&wos[t][0];
#pragma unroll
        for (int i = 0; i < 32; i++) ffma2(accp[i], xp, wp[i]);
    }

    const float* feat = ((sb >> 1) ? fpet : fct) + (sb & 1) * (CH * L);
    float* o = out + (size_t)sb * CH * L + v;
#pragma unroll
    for (int i = 0; i < 32; i++) {
        float lo, hi;
        unpack2(accp[i], lo, hi);
        int c0 = 2 * i, c1 = 2 * i + 1;
        o[(size_t)c0 * L] = feat[(size_t)c0 * L + v] + bo[c0] + lo;
        o[(size_t)c1 * L] = feat[(size_t)c1 * L + v] + bo[c1] + hi;
    }
}

// ---------------------------------------------------------------------------
extern "C" void kernel_launch(void* const* d_in, const int* in_sizes, int n_in,
                              void* d_out, int out_size)
{
    const float* fct  = (const float*)d_in[0];
    const float* fpet = (const float*)d_in[1];
    const float* wq   = (const float*)d_in[2];
    const float* bq   = (const float*)d_in[3];
    const float* wk   = (const float*)d_in[4];
    const float* bk   = (const float*)d_in[5];
    const float* wv   = (const float*)d_in[6];
    const float* bv   = (const float*)d_in[7];
    const float* wo   = (const float*)d_in[8];
    const float* bo   = (const float*)d_in[9];
    float* out = (float*)d_out;

    qkv_kernel<<<dim3(L, NSB), 128>>>(fct, fpet, wq, bq, wk, bk, wv, bv);
    attn_kernel<<<dim3(32, NH, NSB), 128>>>();
    out_kernel<<<dim3(32, NSB), 128>>>(fct, fpet, wo, bo, out);
}

// round 3
// speedup vs baseline: 1.7300x; 1.7300x over previous
#include <cuda_runtime.h>
#include <cuda_bf16.h>
#include <cstdint>

#define L    4096
#define TD   128
#define CH   64
#define NH   4
#define HD   32
#define NSB  4

// Scratch (static device globals allowed; no runtime allocation)
static __device__ float Qbuf[NSB * L * TD];                 // fp32 q (residual)
static __device__ float Fbuf[NSB * L * TD];                 // fused = (attn + q) * 0.5
static __device__ __nv_bfloat16 Qbf[NSB * NH * L * HD];     // [sb][h][l][d]
static __device__ __nv_bfloat16 Kbf[NSB * NH * L * HD];
static __device__ __nv_bfloat16 Vbf[NSB * NH * L * HD];

// ---------------------------------------------------------------------------
// helpers
// ---------------------------------------------------------------------------
__device__ __forceinline__ void ffma2(unsigned long long &d,
                                      unsigned long long a,
                                      unsigned long long b) {
    asm("fma.rn.f32x2 %0, %1, %2, %0;" : "+l"(d) : "l"(a), "l"(b));
}
__device__ __forceinline__ unsigned long long pack2(float x) {
    unsigned long long r;
    unsigned int u = __float_as_uint(x);
    asm("mov.b64 %0, {%1, %1};" : "=l"(r) : "r"(u));
    return r;
}
__device__ __forceinline__ void unpack2(unsigned long long d, float &lo, float &hi) {
    unsigned int a, b;
    asm("mov.b64 {%0, %1}, %2;" : "=r"(a), "=r"(b) : "l"(d));
    lo = __uint_as_float(a);
    hi = __uint_as_float(b);
}
// bf16x2 pack: low half = lo, high half = hi
__device__ __forceinline__ uint32_t pkbf(float lo, float hi) {
    uint32_t d;
    asm("cvt.rn.bf16x2.f32 %0, %1, %2;" : "=r"(d) : "f"(hi), "f"(lo));
    return d;
}

#define LDSM_X4(r, addr) \
    asm volatile("ldmatrix.sync.aligned.m8n8.x4.shared.b16 {%0,%1,%2,%3}, [%4];" \
        : "=r"((r)[0]), "=r"((r)[1]), "=r"((r)[2]), "=r"((r)[3]) : "r"(addr))

#define LDSM_X4_T(r, addr) \
    asm volatile("ldmatrix.sync.aligned.m8n8.x4.trans.shared.b16 {%0,%1,%2,%3}, [%4];" \
        : "=r"((r)[0]), "=r"((r)[1]), "=r"((r)[2]), "=r"((r)[3]) : "r"(addr))

#define MMA_BF16(d, a, b0, b1) \
    asm volatile("mma.sync.aligned.m16n8k16.row.col.f32.bf16.bf16.f32 " \
        "{%0,%1,%2,%3}, {%4,%5,%6,%7}, {%8,%9}, {%0,%1,%2,%3};" \
        : "+f"((d)[0]), "+f"((d)[1]), "+f"((d)[2]), "+f"((d)[3]) \
        : "r"((a)[0]), "r"((a)[1]), "r"((a)[2]), "r"((a)[3]), \
          "r"(b0), "r"(b1))

// ---------------------------------------------------------------------------
// Kernel A: QKV projection + bf16 repack to [sb][h][l][d]
// grid: (L, NSB), block: 128 (thread = output channel t)
// ---------------------------------------------------------------------------
__global__ void __launch_bounds__(128) qkv_kernel(
    const float* __restrict__ fct, const float* __restrict__ fpet,
    const float* __restrict__ wq, const float* __restrict__ bq,
    const float* __restrict__ wk, const float* __restrict__ bk,
    const float* __restrict__ wv, const float* __restrict__ bv)
{
    int l  = blockIdx.x;
    int sb = blockIdx.y;
    const float* feat = ((sb >> 1) ? fpet : fct) + (sb & 1) * (CH * L);

    __shared__ float xs[CH];
    int t = threadIdx.x;
    if (t < CH) xs[t] = feat[t * L + l];
    __syncthreads();

    float aq = bq[t], ak = bk[t], av = bv[t];
    const float* wqr = wq + t * CH;
    const float* wkr = wk + t * CH;
    const float* wvr = wv + t * CH;
#pragma unroll
    for (int c = 0; c < CH; c++) {
        float x = xs[c];
        aq = fmaf(x, wqr[c], aq);
        ak = fmaf(x, wkr[c], ak);
        av = fmaf(x, wvr[c], av);
    }
    Qbuf[(sb * L + l) * TD + t] = aq;

    int h = t >> 5, d = t & 31;
    size_t bi = ((size_t)(sb * NH + h) * L + l) * HD + d;
    Qbf[bi] = __float2bfloat16(aq);
    Kbf[bi] = __float2bfloat16(ak);
    Vbf[bi] = __float2bfloat16(av);
}

// ---------------------------------------------------------------------------
// Kernel B: flash cross-attention on mma.sync (bf16 HMMA).
// grid: (L/128, NH, NSB), block 256 (8 warps; warp = 16 query rows).
// ---------------------------------------------------------------------------
__global__ void __launch_bounds__(256) attn_mma_kernel()
{
    const float SCALEV = 0.17677669529663687f;   // 32^-0.5

    // 128 rows x 80B stride (64B payload), K then V
    __shared__ __align__(128) uint8_t sm[2 * 128 * 80];

    int tid  = threadIdx.x;
    int w    = tid >> 5;
    int lane = tid & 31;
    int g    = lane >> 2;      // row group 0..7
    int tg   = lane & 3;       // thread-in-group

    int qt = blockIdx.x, h = blockIdx.y, sb = blockIdx.z;
    int kvsb = sb ^ 2;

    const __nv_bfloat16* Kg = Kbf + (size_t)(kvsb * NH + h) * L * HD;
    const __nv_bfloat16* Vg = Vbf + (size_t)(kvsb * NH + h) * L * HD;
    const __nv_bfloat16* Qg = Qbf + ((size_t)(sb * NH + h) * L + qt * 128) * HD;

    uint32_t smK = (uint32_t)__cvta_generic_to_shared(sm);
    uint32_t smV = smK + 128 * 80;

    // ---- stage Q (bf16) through K smem region, grab A-fragments ----
    {
        int row = tid >> 1, half = tid & 1;
        const uint4* src = (const uint4*)(Qg + row * HD + half * 16);
        uint4* dst = (uint4*)(sm + row * 80 + half * 32);
        dst[0] = src[0];
        dst[1] = src[1];
    }
    __syncthreads();
    uint32_t qa0[4], qa1[4];
    {
        uint32_t a = smK + (uint32_t)(w * 16 + (lane & 15)) * 80 + ((lane >> 4) << 4);
        LDSM_X4(qa0, a);        // dims 0-15
        LDSM_X4(qa1, a + 32);   // dims 16-31
    }
    __syncthreads();

    float oacc[4][4];
#pragma unroll
    for (int i = 0; i < 4; i++)
#pragma unroll
        for (int j = 0; j < 4; j++) oacc[i][j] = 0.0f;
    float rs0 = 0.0f, rs1 = 0.0f;

    int lrow = tid >> 1, lhalf = tid & 1;
    uint32_t ldK = smK + (uint32_t)(lane & 15) * 80 + ((lane >> 4) << 4);
    uint32_t ldV = smV + (uint32_t)(lane & 15) * 80 + ((lane >> 4) << 4);

    for (int kt = 0; kt < 32; kt++) {
        // ---- stage K/V tile (128 keys x 32 dims bf16) ----
        {
            const uint4* ks = (const uint4*)(Kg + (size_t)(kt * 128 + lrow) * HD + lhalf * 16);
            const uint4* vs = (const uint4*)(Vg + (size_t)(kt * 128 + lrow) * HD + lhalf * 16);
            uint4 k0 = ks[0], k1 = ks[1], v0 = vs[0], v1 = vs[1];
            uint4* kd = (uint4*)(sm + lrow * 80 + lhalf * 32);
            uint4* vd = (uint4*)(sm + 128 * 80 + lrow * 80 + lhalf * 32);
            kd[0] = k0; kd[1] = k1;
            vd[0] = v0; vd[1] = v1;
        }
        __syncthreads();

#pragma unroll
        for (int kc = 0; kc < 8; kc++) {
            // S = Q K^T for keys kc*16..+15 (2 n-tiles of 8)
            uint32_t bk0[4], bk1[4];
            LDSM_X4(bk0, ldK + kc * 1280);        // dims 0-15
            LDSM_X4(bk1, ldK + kc * 1280 + 32);   // dims 16-31
            float d0[4] = {0.f, 0.f, 0.f, 0.f};
            float d1[4] = {0.f, 0.f, 0.f, 0.f};
            MMA_BF16(d0, qa0, bk0[0], bk0[2]);
            MMA_BF16(d0, qa1, bk1[0], bk1[2]);
            MMA_BF16(d1, qa0, bk0[1], bk0[3]);
            MMA_BF16(d1, qa1, bk1[1], bk1[3]);

            // softmax numerator (no max-subtraction; logits tiny)
            float e00 = __expf(d0[0] * SCALEV), e01 = __expf(d0[1] * SCALEV);
            float e02 = __expf(d0[2] * SCALEV), e03 = __expf(d0[3] * SCALEV);
            float e10 = __expf(d1[0] * SCALEV), e11 = __expf(d1[1] * SCALEV);
            float e12 = __expf(d1[2] * SCALEV), e13 = __expf(d1[3] * SCALEV);
            rs0 += (e00 + e01) + (e10 + e11);
            rs1 += (e02 + e03) + (e12 + e13);

            // P as A-fragments (k = 16 keys of this chunk)
            uint32_t pa[4];
            pa[0] = pkbf(e00, e01);
            pa[1] = pkbf(e02, e03);
            pa[2] = pkbf(e10, e11);
            pa[3] = pkbf(e12, e13);

            // O += P V  (4 n-tiles of 8 dims)
            uint32_t bv0[4], bv1[4];
            LDSM_X4_T(bv0, ldV + kc * 1280);        // dims 0-15
            LDSM_X4_T(bv1, ldV + kc * 1280 + 32);   // dims 16-31
            MMA_BF16(oacc[0], pa, bv0[0], bv0[1]);
            MMA_BF16(oacc[1], pa, bv0[2], bv0[3]);
            MMA_BF16(oacc[2], pa, bv1[0], bv1[1]);
            MMA_BF16(oacc[3], pa, bv1[2], bv1[3]);
        }
        __syncthreads();
    }

    // ---- normalize, residual, write Fbuf ----
    rs0 += __shfl_xor_sync(0xFFFFFFFFu, rs0, 1);
    rs0 += __shfl_xor_sync(0xFFFFFFFFu, rs0, 2);
    rs1 += __shfl_xor_sync(0xFFFFFFFFu, rs1, 1);
    rs1 += __shfl_xor_sync(0xFFFFFFFFu, rs1, 2);
    float inv0 = 1.0f / rs0;
    float inv1 = 1.0f / rs1;

    int qrow = qt * 128 + w * 16 + g;
    const float* qsrc = Qbuf + ((size_t)sb * L + qrow) * TD + h * HD;
    float* fo = Fbuf + ((size_t)sb * L + qrow) * TD + h * HD;

#pragma unroll
    for (int nd = 0; nd < 4; nd++) {
        int col = nd * 8 + tg * 2;
        float2 q0 = *(const float2*)(qsrc + col);
        float2 r0;
        r0.x = 0.5f * (oacc[nd][0] * inv0 + q0.x);
        r0.y = 0.5f * (oacc[nd][1] * inv0 + q0.y);
        *(float2*)(fo + col) = r0;

        float2 q1 = *(const float2*)(qsrc + 8 * TD + col);
        float2 r1;
        r1.x = 0.5f * (oacc[nd][2] * inv1 + q1.x);
        r1.y = 0.5f * (oacc[nd][3] * inv1 + q1.y);
        *(float2*)(fo + 8 * TD + col) = r1;
    }
}

// ---------------------------------------------------------------------------
// Kernel C: output projection + residual (unchanged, ~8 us)
// ---------------------------------------------------------------------------
__global__ void __launch_bounds__(128) out_kernel(
    const float* __restrict__ fct, const float* __restrict__ fpet,
    const float* __restrict__ wo, const float* __restrict__ bo,
    float* __restrict__ out)
{
    int vt = blockIdx.x;
    int sb = blockIdx.y;
    int tid = threadIdx.x;
    int v = vt * 128 + tid;

    __shared__ float wos[128][66];
    for (int idx = tid; idx < 128 * 64; idx += 128) {
        int c = idx >> 7;
        int t = idx & 127;
        wos[t][c] = wo[idx];
    }
    __syncthreads();

    unsigned long long accp[32];
#pragma unroll
    for (int i = 0; i < 32; i++) accp[i] = 0ull;

    const float* F = Fbuf + (size_t)sb * L * TD;
#pragma unroll 4
    for (int t = 0; t < 128; t++) {
        float x = F[(size_t)t * L + v];
        unsigned long long xp = pack2(x);
        const unsigned long long* wp = (const unsigned long long*)&wos[t][0];
#pragma unroll
        for (int i = 0; i < 32; i++) ffma2(accp[i], xp, wp[i]);
    }

    const float* feat = ((sb >> 1) ? fpet : fct) + (sb & 1) * (CH * L);
    float* o = out + (size_t)sb * CH * L + v;
#pragma unroll
    for (int i = 0; i < 32; i++) {
        float lo, hi;
        unpack2(accp[i], lo, hi);
        int c0 = 2 * i, c1 = 2 * i + 1;
        o[(size_t)c0 * L] = feat[(size_t)c0 * L + v] + bo[c0] + lo;
        o[(size_t)c1 * L] = feat[(size_t)c1 * L + v] + bo[c1] + hi;
    }
}

// ---------------------------------------------------------------------------
extern "C" void kernel_launch(void* const* d_in, const int* in_sizes, int n_in,
                              void* d_out, int out_size)
{
    const float* fct  = (const float*)d_in[0];
    const float* fpet = (const float*)d_in[1];
    const float* wq   = (const float*)d_in[2];
    const float* bq   = (const float*)d_in[3];
    const float* wk   = (const float*)d_in[4];
    const float* bk   = (const float*)d_in[5];
    const float* wv   = (const float*)d_in[6];
    const float* bv   = (const float*)d_in[7];
    const float* wo   = (const float*)d_in[8];
    const float* bo   = (const float*)d_in[9];
    float* out = (float*)d_out;

    qkv_kernel<<<dim3(L, NSB), 128>>>(fct, fpet, wq, bq, wk, bk, wv, bv);
    attn_mma_kernel<<<dim3(L / 128, NH, NSB), 256>>>();
    out_kernel<<<dim3(L / 128, NSB), 128>>>(fct, fpet, wo, bo, out);
}

// round 4
// speedup vs baseline: 1.7351x; 1.0029x over previous
#include <cuda_runtime.h>
#include <cuda_bf16.h>
#include <cstdint>

#define L    4096
#define TD   128
#define CH   64
#define NH   4
#define HD   32
#define NSB  4

// Scratch (static device globals allowed; no runtime allocation)
static __device__ float Qbuf[NSB * L * TD];                 // fp32 q (residual)
static __device__ float Fbuf[NSB * L * TD];                 // fused = (attn + q) * 0.5
static __device__ __nv_bfloat16 Qbf[NSB * NH * L * HD];     // [sb][h][l][d]
static __device__ __nv_bfloat16 Kbf[NSB * NH * L * HD];
static __device__ __nv_bfloat16 Vbf[NSB * NH * L * HD];

// ---------------------------------------------------------------------------
// helpers
// ---------------------------------------------------------------------------
__device__ __forceinline__ void ffma2(unsigned long long &d,
                                      unsigned long long a,
                                      unsigned long long b) {
    asm("fma.rn.f32x2 %0, %1, %2, %0;" : "+l"(d) : "l"(a), "l"(b));
}
__device__ __forceinline__ unsigned long long pack2(float x) {
    unsigned long long r;
    unsigned int u = __float_as_uint(x);
    asm("mov.b64 %0, {%1, %1};" : "=l"(r) : "r"(u));
    return r;
}
__device__ __forceinline__ void unpack2(unsigned long long d, float &lo, float &hi) {
    unsigned int a, b;
    asm("mov.b64 {%0, %1}, %2;" : "=r"(a), "=r"(b) : "l"(d));
    lo = __uint_as_float(a);
    hi = __uint_as_float(b);
}
// bf16x2 pack: low half = lo, high half = hi
__device__ __forceinline__ uint32_t pkbf(float lo, float hi) {
    uint32_t d;
    asm("cvt.rn.bf16x2.f32 %0, %1, %2;" : "=r"(d) : "f"(hi), "f"(lo));
    return d;
}

#define LDSM_X4(r, addr) \
    asm volatile("ldmatrix.sync.aligned.m8n8.x4.shared.b16 {%0,%1,%2,%3}, [%4];" \
        : "=r"((r)[0]), "=r"((r)[1]), "=r"((r)[2]), "=r"((r)[3]) : "r"(addr))

#define LDSM_X4_T(r, addr) \
    asm volatile("ldmatrix.sync.aligned.m8n8.x4.trans.shared.b16 {%0,%1,%2,%3}, [%4];" \
        : "=r"((r)[0]), "=r"((r)[1]), "=r"((r)[2]), "=r"((r)[3]) : "r"(addr))

#define MMA_BF16(d, a, b0, b1) \
    asm volatile("mma.sync.aligned.m16n8k16.row.col.f32.bf16.bf16.f32 " \
        "{%0,%1,%2,%3}, {%4,%5,%6,%7}, {%8,%9}, {%0,%1,%2,%3};" \
        : "+f"((d)[0]), "+f"((d)[1]), "+f"((d)[2]), "+f"((d)[3]) \
        : "r"((a)[0]), "r"((a)[1]), "r"((a)[2]), "r"((a)[3]), \
          "r"(b0), "r"(b1))

// ---------------------------------------------------------------------------
// Kernel A: QKV projection + bf16 repack to [sb][h][l][d]
// grid: (L, NSB), block: 128 (thread = output channel t)
// ---------------------------------------------------------------------------
__global__ void __launch_bounds__(128) qkv_kernel(
    const float* __restrict__ fct, const float* __restrict__ fpet,
    const float* __restrict__ wq, const float* __restrict__ bq,
    const float* __restrict__ wk, const float* __restrict__ bk,
    const float* __restrict__ wv, const float* __restrict__ bv)
{
    int l  = blockIdx.x;
    int sb = blockIdx.y;
    const float* feat = ((sb >> 1) ? fpet : fct) + (sb & 1) * (CH * L);

    __shared__ float xs[CH];
    int t = threadIdx.x;
    if (t < CH) xs[t] = feat[t * L + l];
    __syncthreads();

    float aq = bq[t], ak = bk[t], av = bv[t];
    const float* wqr = wq + t * CH;
    const float* wkr = wk + t * CH;
    const float* wvr = wv + t * CH;
#pragma unroll
    for (int c = 0; c < CH; c++) {
        float x = xs[c];
        aq = fmaf(x, wqr[c], aq);
        ak = fmaf(x, wkr[c], ak);
        av = fmaf(x, wvr[c], av);
    }
    Qbuf[(sb * L + l) * TD + t] = aq;

    int h = t >> 5, d = t & 31;
    size_t bi = ((size_t)(sb * NH + h) * L + l) * HD + d;
    Qbf[bi] = __float2bfloat16(aq);
    Kbf[bi] = __float2bfloat16(ak);
    Vbf[bi] = __float2bfloat16(av);
}

// ---------------------------------------------------------------------------
// Kernel B: flash cross-attention on mma.sync (bf16 HMMA).
// grid: (L/128, NH, NSB), block 256 (8 warps; warp = 16 query rows).
// ---------------------------------------------------------------------------
__global__ void __launch_bounds__(256) attn_mma_kernel()
{
    const float SCALEV = 0.17677669529663687f;   // 32^-0.5

    // 128 rows x 80B stride (64B payload), K then V
    __shared__ __align__(128) uint8_t sm[2 * 128 * 80];

    int tid  = threadIdx.x;
    int w    = tid >> 5;
    int lane = tid & 31;
    int g    = lane >> 2;      // row group 0..7
    int tg   = lane & 3;       // thread-in-group

    int qt = blockIdx.x, h = blockIdx.y, sb = blockIdx.z;
    int kvsb = sb ^ 2;

    const __nv_bfloat16* Kg = Kbf + (size_t)(kvsb * NH + h) * L * HD;
    const __nv_bfloat16* Vg = Vbf + (size_t)(kvsb * NH + h) * L * HD;
    const __nv_bfloat16* Qg = Qbf + ((size_t)(sb * NH + h) * L + qt * 128) * HD;

    uint32_t smK = (uint32_t)__cvta_generic_to_shared(sm);
    uint32_t smV = smK + 128 * 80;

    // ---- stage Q (bf16) through K smem region, grab A-fragments ----
    {
        int row = tid >> 1, half = tid & 1;
        const uint4* src = (const uint4*)(Qg + row * HD + half * 16);
        uint4* dst = (uint4*)(sm + row * 80 + half * 32);
        dst[0] = src[0];
        dst[1] = src[1];
    }
    __syncthreads();
    uint32_t qa0[4], qa1[4];
    {
        uint32_t a = smK + (uint32_t)(w * 16 + (lane & 15)) * 80 + ((lane >> 4) << 4);
        LDSM_X4(qa0, a);        // dims 0-15
        LDSM_X4(qa1, a + 32);   // dims 16-31
    }
    __syncthreads();

    float oacc[4][4];
#pragma unroll
    for (int i = 0; i < 4; i++)
#pragma unroll
        for (int j = 0; j < 4; j++) oacc[i][j] = 0.0f;
    float rs0 = 0.0f, rs1 = 0.0f;

    int lrow = tid >> 1, lhalf = tid & 1;
    uint32_t ldK = smK + (uint32_t)(lane & 15) * 80 + ((lane >> 4) << 4);
    uint32_t ldV = smV + (uint32_t)(lane & 15) * 80 + ((lane >> 4) << 4);

    for (int kt = 0; kt < 32; kt++) {
        // ---- stage K/V tile (128 keys x 32 dims bf16) ----
        {
            const uint4* ks = (const uint4*)(Kg + (size_t)(kt * 128 + lrow) * HD + lhalf * 16);
            const uint4* vs = (const uint4*)(Vg + (size_t)(kt * 128 + lrow) * HD + lhalf * 16);
            uint4 k0 = ks[0], k1 = ks[1], v0 = vs[0], v1 = vs[1];
            uint4* kd = (uint4*)(sm + lrow * 80 + lhalf * 32);
            uint4* vd = (uint4*)(sm + 128 * 80 + lrow * 80 + lhalf * 32);
            kd[0] = k0; kd[1] = k1;
            vd[0] = v0; vd[1] = v1;
        }
        __syncthreads();

#pragma unroll
        for (int kc = 0; kc < 8; kc++) {
            // S = Q K^T for keys kc*16..+15 (2 n-tiles of 8)
            uint32_t bk0[4], bk1[4];
            LDSM_X4(bk0, ldK + kc * 1280);        // dims 0-15
            LDSM_X4(bk1, ldK + kc * 1280 + 32);   // dims 16-31
            float d0[4] = {0.f, 0.f, 0.f, 0.f};
            float d1[4] = {0.f, 0.f, 0.f, 0.f};
            MMA_BF16(d0, qa0, bk0[0], bk0[2]);
            MMA_BF16(d0, qa1, bk1[0], bk1[2]);
            MMA_BF16(d1, qa0, bk0[1], bk0[3]);
            MMA_BF16(d1, qa1, bk1[1], bk1[3]);

            // softmax numerator (no max-subtraction; logits tiny)
            float e00 = __expf(d0[0] * SCALEV), e01 = __expf(d0[1] * SCALEV);
            float e02 = __expf(d0[2] * SCALEV), e03 = __expf(d0[3] * SCALEV);
            float e10 = __expf(d1[0] * SCALEV), e11 = __expf(d1[1] * SCALEV);
            float e12 = __expf(d1[2] * SCALEV), e13 = __expf(d1[3] * SCALEV);
            rs0 += (e00 + e01) + (e10 + e11);
            rs1 += (e02 + e03) + (e12 + e13);

            // P as A-fragments (k = 16 keys of this chunk)
            uint32_t pa[4];
            pa[0] = pkbf(e00, e01);
            pa[1] = pkbf(e02, e03);
            pa[2] = pkbf(e10, e11);
            pa[3] = pkbf(e12, e13);

            // O += P V  (4 n-tiles of 8 dims)
            uint32_t bv0[4], bv1[4];
            LDSM_X4_T(bv0, ldV + kc * 1280);        // dims 0-15
            LDSM_X4_T(bv1, ldV + kc * 1280 + 32);   // dims 16-31
            MMA_BF16(oacc[0], pa, bv0[0], bv0[1]);
            MMA_BF16(oacc[1], pa, bv0[2], bv0[3]);
            MMA_BF16(oacc[2], pa, bv1[0], bv1[1]);
            MMA_BF16(oacc[3], pa, bv1[2], bv1[3]);
        }
        __syncthreads();
    }

    // ---- normalize, residual, write Fbuf ----
    rs0 += __shfl_xor_sync(0xFFFFFFFFu, rs0, 1);
    rs0 += __shfl_xor_sync(0xFFFFFFFFu, rs0, 2);
    rs1 += __shfl_xor_sync(0xFFFFFFFFu, rs1, 1);
    rs1 += __shfl_xor_sync(0xFFFFFFFFu, rs1, 2);
    float inv0 = 1.0f / rs0;
    float inv1 = 1.0f / rs1;

    int qrow = qt * 128 + w * 16 + g;
    const float* qsrc = Qbuf + ((size_t)sb * L + qrow) * TD + h * HD;
    float* fo = Fbuf + ((size_t)sb * L + qrow) * TD + h * HD;

#pragma unroll
    for (int nd = 0; nd < 4; nd++) {
        int col = nd * 8 + tg * 2;
        float2 q0 = *(const float2*)(qsrc + col);
        float2 r0;
        r0.x = 0.5f * (oacc[nd][0] * inv0 + q0.x);
        r0.y = 0.5f * (oacc[nd][1] * inv0 + q0.y);
        *(float2*)(fo + col) = r0;

        float2 q1 = *(const float2*)(qsrc + 8 * TD + col);
        float2 r1;
        r1.x = 0.5f * (oacc[nd][2] * inv1 + q1.x);
        r1.y = 0.5f * (oacc[nd][3] * inv1 + q1.y);
        *(float2*)(fo + 8 * TD + col) = r1;
    }
}

// ---------------------------------------------------------------------------
// Kernel C: output projection + residual (unchanged, ~8 us)
// ---------------------------------------------------------------------------
__global__ void __launch_bounds__(128) out_kernel(
    const float* __restrict__ fct, const float* __restrict__ fpet,
    const float* __restrict__ wo, const float* __restrict__ bo,
    float* __restrict__ out)
{
    int vt = blockIdx.x;
    int sb = blockIdx.y;
    int tid = threadIdx.x;
    int v = vt * 128 + tid;

    __shared__ float wos[128][66];
    for (int idx = tid; idx < 128 * 64; idx += 128) {
        int c = idx >> 7;
        int t = idx & 127;
        wos[t][c] = wo[idx];
    }
    __syncthreads();

    unsigned long long accp[32];
#pragma unroll
    for (int i = 0; i < 32; i++) accp[i] = 0ull;

    const float* F = Fbuf + (size_t)sb * L * TD;
#pragma unroll 4
    for (int t = 0; t < 128; t++) {
        float x = F[(size_t)t * L + v];
        unsigned long long xp = pack2(x);
        const unsigned long long* wp = (const unsigned long long*)&wos[t][0];
#pragma unroll
        for (int i = 0; i < 32; i++) ffma2(accp[i], xp, wp[i]);
    }

    const float* feat = ((sb >> 1) ? fpet : fct) + (sb & 1) * (CH * L);
    float* o = out + (size_t)sb * CH * L + v;
#pragma unroll
    for (int i = 0; i < 32; i++) {
        float lo, hi;
        unpack2(accp[i], lo, hi);
        int c0 = 2 * i, c1 = 2 * i + 1;
        o[(size_t)c0 * L] = feat[(size_t)c0 * L + v] + bo[c0] + lo;
        o[(size_t)c1 * L] = feat[(size_t)c1 * L + v] + bo[c1] + hi;
    }
}

// ---------------------------------------------------------------------------
extern "C" void kernel_launch(void* const* d_in, const int* in_sizes, int n_in,
                              void* d_out, int out_size)
{
    const float* fct  = (const float*)d_in[0];
    const float* fpet = (const float*)d_in[1];
    const float* wq   = (const float*)d_in[2];
    const float* bq   = (const float*)d_in[3];
    const float* wk   = (const float*)d_in[4];
    const float* bk   = (const float*)d_in[5];
    const float* wv   = (const float*)d_in[6];
    const float* bv   = (const float*)d_in[7];
    const float* wo   = (const float*)d_in[8];
    const float* bo   = (const float*)d_in[9];
    float* out = (float*)d_out;

    qkv_kernel<<<dim3(L, NSB), 128>>>(fct, fpet, wq, bq, wk, bk, wv, bv);
    attn_mma_kernel<<<dim3(L / 128, NH, NSB), 256>>>();
    out_kernel<<<dim3(L / 128, NSB), 128>>>(fct, fpet, wo, bo, out);
}